// round 1
// baseline (speedup 1.0000x reference)
#include <cuda_runtime.h>
#include <cstdint>

#define RES    300
#define NCOMP  48
#define NFEAT  27
#define NPAD   28          // pad 27 -> 28 so each W row is 7 x 16B
#define KTOT   (3*NCOMP)   // 144

// Scratch: channel-last transposed copies (allowed: __device__ globals, no alloc).
__device__ __align__(16) float g_planesT[3u * RES * RES * NCOMP]; // [i][y][x][c]
__device__ __align__(16) float g_linesT [3u * RES * NCOMP];       // [i][r][c]

// ---------------------------------------------------------------------------
// Transpose planes (3,48,300,300) -> (3,300,300,48) via shared tile.
// grid = (10 xtiles, 300 y, 3 i), block = 256
// ---------------------------------------------------------------------------
__global__ void transpose_planes_kernel(const float* __restrict__ planes) {
    __shared__ float tile[NCOMP][33];
    const int i  = blockIdx.z;
    const int y  = blockIdx.y;
    const int xt = blockIdx.x * 32;
    const int t  = threadIdx.x;
    const int tx = t & 31;
    const int tc = t >> 5;             // 0..7
    const int x  = xt + tx;

    #pragma unroll
    for (int r = 0; r < 6; r++) {
        const int c = tc + 8 * r;      // covers 0..47
        if (x < RES)
            tile[c][tx] = planes[(((size_t)i * NCOMP + c) * RES + y) * RES + x];
    }
    __syncthreads();

    const int nx = min(32, RES - xt);
    float* outb = g_planesT + (((size_t)i * RES + y) * RES + xt) * NCOMP;
    for (int e = t; e < nx * NCOMP; e += 256) {
        const int xl = e / NCOMP;
        const int c  = e - xl * NCOMP;
        outb[e] = tile[c][xl];         // out layout [x][c] contiguous -> coalesced
    }
}

// Transpose lines (3,48,300,1) -> (3,300,48). Output-coalesced.
__global__ void transpose_lines_kernel(const float* __restrict__ lines) {
    const int e = blockIdx.x * 256 + threadIdx.x;
    if (e >= 3 * RES * NCOMP) return;
    const int c  = e % NCOMP;
    const int ir = e / NCOMP;
    const int r  = ir % RES;
    const int i  = ir / RES;
    g_linesT[e] = lines[((size_t)i * NCOMP + c) * RES + r];
}

// ---------------------------------------------------------------------------
// Packed f32x2 helpers (Blackwell): 2 fp32 FMAs per instruction.
// ---------------------------------------------------------------------------
__device__ __forceinline__ void fma2(unsigned long long& d,
                                     unsigned long long a,
                                     unsigned long long b) {
    asm("fma.rn.f32x2 %0, %1, %2, %0;" : "+l"(d) : "l"(a), "l"(b));
}
__device__ __forceinline__ unsigned long long pack2(float f) {
    unsigned long long r;
    asm("mov.b64 %0, {%1, %1};" : "=l"(r) : "f"(f));
    return r;
}
__device__ __forceinline__ void unpack2(unsigned long long v, float& lo, float& hi) {
    asm("mov.b64 {%0, %1}, %2;" : "=f"(lo), "=f"(hi) : "l"(v));
}

// Per-channel: bilinear*line feature, then 14 packed FMAs into acc (28 lanes of j).
__device__ __forceinline__ void do_channel(float v00, float v01, float v10, float v11,
                                           float L0, float L1,
                                           float w00, float w01, float w10, float w11,
                                           float lw0, float lw1,
                                           const float* __restrict__ wrow,
                                           unsigned long long* acc) {
    const float pf = w00 * v00 + w01 * v01 + w10 * v10 + w11 * v11;
    const float lf = lw0 * L0 + lw1 * L1;
    const unsigned long long ff = pack2(pf * lf);
    const ulonglong2* wr = reinterpret_cast<const ulonglong2*>(wrow);
    #pragma unroll
    for (int q = 0; q < 7; q++) {
        ulonglong2 w = wr[q];            // LDS.128, uniform address -> broadcast
        fma2(acc[2 * q],     w.x, ff);
        fma2(acc[2 * q + 1], w.y, ff);
    }
}

// ---------------------------------------------------------------------------
// Main: one thread per point.
// ---------------------------------------------------------------------------
__global__ __launch_bounds__(256)
void tvm_main_kernel(const float* __restrict__ xyz,
                     const float* __restrict__ basisW,
                     float* __restrict__ out,
                     int npts) {
    __shared__ __align__(16) float sW[KTOT * NPAD]; // sW[k*28 + j] = W[j][k], j==27 -> 0

    for (int e = threadIdx.x; e < KTOT * NPAD; e += 256) {
        const int k = e / NPAD;
        const int j = e - k * NPAD;
        sW[e] = (j < NFEAT) ? basisW[j * KTOT + k] : 0.0f;
    }
    __syncthreads();

    const int n = blockIdx.x * 256 + threadIdx.x;
    if (n >= npts) return;

    const float p0 = xyz[3 * n + 0];
    const float p1 = xyz[3 * n + 1];
    const float p2 = xyz[3 * n + 2];

    unsigned long long acc[14];
    #pragma unroll
    for (int q = 0; q < 14; q++) acc[q] = 0ull;

    // PLANE_AX = ((2,1),(2,0),(1,0)): gx = p[a] (W dim), gy = p[b] (H dim); line at p[i].
    const float gxs[3] = {p2, p2, p1};
    const float gys[3] = {p1, p0, p0};
    const float gzs[3] = {p0, p1, p2};

    #pragma unroll
    for (int i = 0; i < 3; i++) {
        const float sc = 0.5f * (float)(RES - 1);
        const float x = (gxs[i] + 1.0f) * sc;
        const float y = (gys[i] + 1.0f) * sc;
        const float z = (gzs[i] + 1.0f) * sc;
        const float xf = floorf(x), yf = floorf(y), zf = floorf(z);
        const float wx = x - xf, wy = y - yf, wz = z - zf;
        const int x0 = min(max((int)xf, 0), RES - 1); const int x1 = min(x0 + 1, RES - 1);
        const int y0 = min(max((int)yf, 0), RES - 1); const int y1 = min(y0 + 1, RES - 1);
        const int z0 = min(max((int)zf, 0), RES - 1); const int z1 = min(z0 + 1, RES - 1);

        const float w00 = (1.0f - wx) * (1.0f - wy);
        const float w01 = wx * (1.0f - wy);
        const float w10 = (1.0f - wx) * wy;
        const float w11 = wx * wy;
        const float lw0 = 1.0f - wz;
        const float lw1 = wz;

        const float* P = g_planesT + (size_t)i * RES * RES * NCOMP;
        const float4* r00 = (const float4*)(P + ((size_t)y0 * RES + x0) * NCOMP);
        const float4* r01 = (const float4*)(P + ((size_t)y0 * RES + x1) * NCOMP);
        const float4* r10 = (const float4*)(P + ((size_t)y1 * RES + x0) * NCOMP);
        const float4* r11 = (const float4*)(P + ((size_t)y1 * RES + x1) * NCOMP);
        const float4* l0  = (const float4*)(g_linesT + ((size_t)i * RES + z0) * NCOMP);
        const float4* l1  = (const float4*)(g_linesT + ((size_t)i * RES + z1) * NCOMP);
        const float* wb = sW + i * NCOMP * NPAD;

        #pragma unroll 2
        for (int c4 = 0; c4 < NCOMP / 4; c4++) {
            const float4 v00 = r00[c4];
            const float4 v01 = r01[c4];
            const float4 v10 = r10[c4];
            const float4 v11 = r11[c4];
            const float4 L0  = l0[c4];
            const float4 L1  = l1[c4];
            const float* wrow = wb + (c4 * 4) * NPAD;
            do_channel(v00.x, v01.x, v10.x, v11.x, L0.x, L1.x,
                       w00, w01, w10, w11, lw0, lw1, wrow + 0 * NPAD, acc);
            do_channel(v00.y, v01.y, v10.y, v11.y, L0.y, L1.y,
                       w00, w01, w10, w11, lw0, lw1, wrow + 1 * NPAD, acc);
            do_channel(v00.z, v01.z, v10.z, v11.z, L0.z, L1.z,
                       w00, w01, w10, w11, lw0, lw1, wrow + 2 * NPAD, acc);
            do_channel(v00.w, v01.w, v10.w, v11.w, L0.w, L1.w,
                       w00, w01, w10, w11, lw0, lw1, wrow + 3 * NPAD, acc);
        }
    }

    float* o = out + (size_t)n * NFEAT;
    #pragma unroll
    for (int q = 0; q < 13; q++) {
        float lo, hi;
        unpack2(acc[q], lo, hi);
        o[2 * q]     = lo;
        o[2 * q + 1] = hi;
    }
    {
        float lo, hi;
        unpack2(acc[13], lo, hi);
        o[26] = lo;                     // j == 27 is the zero pad, discarded
    }
}

// ---------------------------------------------------------------------------
extern "C" void kernel_launch(void* const* d_in, const int* in_sizes, int n_in,
                              void* d_out, int out_size) {
    const float* xyz    = (const float*)d_in[0];
    const float* planes = (const float*)d_in[1];
    const float* lines  = (const float*)d_in[2];
    const float* basisW = (const float*)d_in[3];
    float* out = (float*)d_out;
    const int npts = in_sizes[0] / 3;

    dim3 tg((RES + 31) / 32, RES, 3);
    transpose_planes_kernel<<<tg, 256>>>(planes);
    transpose_lines_kernel<<<(3 * RES * NCOMP + 255) / 256, 256>>>(lines);
    tvm_main_kernel<<<(npts + 255) / 256, 256>>>(xyz, basisW, out, npts);
}